// round 3
// baseline (speedup 1.0000x reference)
#include <cuda_runtime.h>
#include <cuda_bf16.h>

#define NB 1184   // 8 blocks per SM x 148 SMs
#define NT 256

// Scratch: per-(tensor, block) partial sums of squares + per-row bias sums.
// Every slot is written on every launch -> deterministic, no zeroing needed.
__device__ float g_partials[7 * NB];
__device__ float g_rowsums[128];

__device__ __forceinline__ float block_reduce(float v, float* sdata) {
    int tid = threadIdx.x;
    #pragma unroll
    for (int off = 16; off > 0; off >>= 1)
        v += __shfl_down_sync(0xFFFFFFFFu, v, off);
    if ((tid & 31) == 0) sdata[tid >> 5] = v;
    __syncthreads();
    float r = 0.0f;
    if (tid < (NT / 32)) r = sdata[tid];
    if (tid < 32) {
        #pragma unroll
        for (int off = (NT / 64); off > 0; off >>= 1)
            r += __shfl_down_sync(0xFFFFFFFFu, r, off);
    }
    return r;  // valid in tid 0
}

__global__ __launch_bounds__(NT, 8)
void wr_reduce_kernel(const float* __restrict__ wq, const float* __restrict__ wk,
                      const float* __restrict__ wv, const float* __restrict__ wo,
                      const float* __restrict__ w1, const float* __restrict__ w2,
                      const float* __restrict__ embed, const float* __restrict__ biases,
                      long n0, long n1, long n2, long n3, long n4, long n5, long n6)
{
    __shared__ float sdata[NT / 32];
    const float* ptrs[7] = {wq, wk, wv, wo, w1, w2, embed};
    long ns[7] = {n0, n1, n2, n3, n4, n5, n6};

    const long base   = (long)blockIdx.x * NT + threadIdx.x;
    const long stride = (long)gridDim.x * NT;

    #pragma unroll 1
    for (int t = 0; t < 7; t++) {
        const float* __restrict__ pf = ptrs[t];
        const float4* __restrict__ p = (const float4*)pf;
        const long n    = ns[t];
        const long n4e  = n >> 2;
        float s = 0.0f;
        for (long i = base; i < n4e; i += stride) {
            float4 v = p[i];
            s = fmaf(v.x, v.x, s);
            s = fmaf(v.y, v.y, s);
            s = fmaf(v.z, v.z, s);
            s = fmaf(v.w, v.w, s);
        }
        // scalar tail (n % 4), handled once by block 0 / thread 0 (free; sizes
        // here are all multiples of 4 so this loop is empty in practice)
        if (blockIdx.x == 0 && threadIdx.x == 0) {
            for (long i = n4e << 2; i < n; i++) s = fmaf(pf[i], pf[i], s);
        }
        float r = block_reduce(s, sdata);
        if (threadIdx.x == 0) g_partials[t * NB + blockIdx.x] = r;
        __syncthreads();  // protect sdata for next tensor
    }

    // Bias rows: one block per row (blocks 0..127), 2048 floats = 512 float4
    if (blockIdx.x < 128) {
        const float4* __restrict__ p = (const float4*)(biases) + (long)blockIdx.x * 512;
        float s = 0.0f;
        for (int i = threadIdx.x; i < 512; i += NT) {
            float4 v = p[i];
            s = fmaf(v.x, v.x, s);
            s = fmaf(v.y, v.y, s);
            s = fmaf(v.z, v.z, s);
            s = fmaf(v.w, v.w, s);
        }
        float r = block_reduce(s, sdata);
        if (threadIdx.x == 0) g_rowsums[blockIdx.x] = r;
    }
}

__global__ __launch_bounds__(NT)
void wr_finalize_kernel(float* __restrict__ out)
{
    __shared__ float sdata[NT / 32];
    __shared__ float s_total;
    int tid = threadIdx.x;
    if (tid == 0) s_total = 0.0f;
    __syncthreads();

    #pragma unroll 1
    for (int t = 0; t < 7; t++) {
        float s = 0.0f;
        for (int i = tid; i < NB; i += NT) s += g_partials[t * NB + i];
        float r = block_reduce(s, sdata);
        if (tid == 0) s_total += sqrtf(r);
        __syncthreads();
    }

    // per-row bias norms
    float s2 = 0.0f;
    for (int r = tid; r < 128; r += NT) s2 += sqrtf(g_rowsums[r]);
    float rb = block_reduce(s2, sdata);
    if (tid == 0) {
        float total = s_total + rb;
        out[0] = 0.0001f * (total / 135.0f);  // 7 mats + 128 rows = 135 params
    }
}

extern "C" void kernel_launch(void* const* d_in, const int* in_sizes, int n_in,
                              void* d_out, int out_size)
{
    const float* wq     = (const float*)d_in[0];
    const float* wk     = (const float*)d_in[1];
    const float* wv     = (const float*)d_in[2];
    const float* wo     = (const float*)d_in[3];
    const float* w1     = (const float*)d_in[4];
    const float* w2     = (const float*)d_in[5];
    const float* embed  = (const float*)d_in[6];
    const float* biases = (const float*)d_in[7];

    wr_reduce_kernel<<<NB, NT>>>(wq, wk, wv, wo, w1, w2, embed, biases,
                                 (long)in_sizes[0], (long)in_sizes[1], (long)in_sizes[2],
                                 (long)in_sizes[3], (long)in_sizes[4], (long)in_sizes[5],
                                 (long)in_sizes[6]);
    wr_finalize_kernel<<<1, NT>>>((float*)d_out);
}

// round 6
// speedup vs baseline: 1.0350x; 1.0350x over previous
#include <cuda_runtime.h>
#include <cuda_bf16.h>

#define NB 1184   // 8 blocks per SM x 148 SMs
#define NT 256

// Scratch: per-(tensor, block) partials + per-row bias sums + arrival counter.
// Partials/rowsums: every slot written every launch -> deterministic.
// g_count: incremented to NB then reset to 0 by the last block -> replay-safe.
__device__ float g_partials[7 * NB];
__device__ float g_rowsums[128];
__device__ int   g_count = 0;

__device__ __forceinline__ float block_reduce(float v, float* sdata) {
    int tid = threadIdx.x;
    #pragma unroll
    for (int off = 16; off > 0; off >>= 1)
        v += __shfl_down_sync(0xFFFFFFFFu, v, off);
    if ((tid & 31) == 0) sdata[tid >> 5] = v;
    __syncthreads();
    float r = 0.0f;
    if (tid < (NT / 32)) r = sdata[tid];
    if (tid < 32) {
        #pragma unroll
        for (int off = (NT / 64); off > 0; off >>= 1)
            r += __shfl_down_sync(0xFFFFFFFFu, r, off);
    }
    return r;  // valid in tid 0
}

__global__ __launch_bounds__(NT, 8)
void wr_fused_kernel(const float* __restrict__ wq, const float* __restrict__ wk,
                     const float* __restrict__ wv, const float* __restrict__ wo,
                     const float* __restrict__ w1, const float* __restrict__ w2,
                     const float* __restrict__ embed, const float* __restrict__ biases,
                     long n0, long n1, long n2, long n3, long n4, long n5, long n6,
                     float* __restrict__ out)
{
    __shared__ float sdata[NT / 32];
    const float* ptrs[7] = {wq, wk, wv, wo, w1, w2, embed};
    long ns[7] = {n0, n1, n2, n3, n4, n5, n6};

    const long base   = (long)blockIdx.x * NT + threadIdx.x;
    const long stride = (long)gridDim.x * NT;

    #pragma unroll 1
    for (int t = 0; t < 7; t++) {
        const float* __restrict__ pf = ptrs[t];
        const float4* __restrict__ p = (const float4*)pf;
        const long n   = ns[t];
        const long n4e = n >> 2;

        // 4x unrolled, 4 independent accumulators -> 16 outstanding LDG.128/thread
        float s0 = 0.0f, s1 = 0.0f, s2 = 0.0f, s3 = 0.0f;
        long i = base;
        for (; i + 3 * stride < n4e; i += 4 * stride) {
            float4 a = p[i];
            float4 b = p[i + stride];
            float4 c = p[i + 2 * stride];
            float4 d = p[i + 3 * stride];
            s0 = fmaf(a.x, a.x, s0); s0 = fmaf(a.y, a.y, s0);
            s0 = fmaf(a.z, a.z, s0); s0 = fmaf(a.w, a.w, s0);
            s1 = fmaf(b.x, b.x, s1); s1 = fmaf(b.y, b.y, s1);
            s1 = fmaf(b.z, b.z, s1); s1 = fmaf(b.w, b.w, s1);
            s2 = fmaf(c.x, c.x, s2); s2 = fmaf(c.y, c.y, s2);
            s2 = fmaf(c.z, c.z, s2); s2 = fmaf(c.w, c.w, s2);
            s3 = fmaf(d.x, d.x, s3); s3 = fmaf(d.y, d.y, s3);
            s3 = fmaf(d.z, d.z, s3); s3 = fmaf(d.w, d.w, s3);
        }
        for (; i < n4e; i += stride) {
            float4 v = p[i];
            s0 = fmaf(v.x, v.x, s0); s0 = fmaf(v.y, v.y, s0);
            s0 = fmaf(v.z, v.z, s0); s0 = fmaf(v.w, v.w, s0);
        }
        float s = (s0 + s1) + (s2 + s3);
        // scalar tail (n % 4): empty for these shapes, kept for safety
        if (blockIdx.x == 0 && threadIdx.x == 0) {
            for (long j = n4e << 2; j < n; j++) s = fmaf(pf[j], pf[j], s);
        }
        float r = block_reduce(s, sdata);
        if (threadIdx.x == 0) g_partials[t * NB + blockIdx.x] = r;
        __syncthreads();  // protect sdata for next tensor
    }

    // Bias rows: one block per row (blocks 0..127), 2048 floats = 512 float4
    if (blockIdx.x < 128) {
        const float4* __restrict__ p = (const float4*)(biases) + (long)blockIdx.x * 512;
        float s = 0.0f;
        for (int i = threadIdx.x; i < 512; i += NT) {
            float4 v = p[i];
            s = fmaf(v.x, v.x, s); s = fmaf(v.y, v.y, s);
            s = fmaf(v.z, v.z, s); s = fmaf(v.w, v.w, s);
        }
        float r = block_reduce(s, sdata);
        if (threadIdx.x == 0) g_rowsums[blockIdx.x] = r;
        __syncthreads();
    }

    // ---- last-block finalize (partials are L2-hot) ----
    __shared__ bool is_last;
    __threadfence();
    if (threadIdx.x == 0) {
        int c = atomicAdd(&g_count, 1);
        is_last = (c == (int)gridDim.x - 1);
    }
    __syncthreads();
    if (!is_last) return;

    __shared__ float s_total;
    int tid = threadIdx.x;
    if (tid == 0) s_total = 0.0f;
    __syncthreads();

    #pragma unroll 1
    for (int t = 0; t < 7; t++) {
        float s = 0.0f;
        #pragma unroll 4
        for (int i = tid; i < NB; i += NT) s += g_partials[t * NB + i];
        float r = block_reduce(s, sdata);
        if (tid == 0) s_total += sqrtf(r);
        __syncthreads();
    }

    float s2v = 0.0f;
    for (int r = tid; r < 128; r += NT) s2v += sqrtf(g_rowsums[r]);
    float rb = block_reduce(s2v, sdata);
    if (tid == 0) {
        out[0] = 0.0001f * ((s_total + rb) / 135.0f);  // 7 mats + 128 rows
        g_count = 0;  // reset for next graph replay
    }
}

extern "C" void kernel_launch(void* const* d_in, const int* in_sizes, int n_in,
                              void* d_out, int out_size)
{
    const float* wq     = (const float*)d_in[0];
    const float* wk     = (const float*)d_in[1];
    const float* wv     = (const float*)d_in[2];
    const float* wo     = (const float*)d_in[3];
    const float* w1     = (const float*)d_in[4];
    const float* w2     = (const float*)d_in[5];
    const float* embed  = (const float*)d_in[6];
    const float* biases = (const float*)d_in[7];

    wr_fused_kernel<<<NB, NT>>>(wq, wk, wv, wo, w1, w2, embed, biases,
                                (long)in_sizes[0], (long)in_sizes[1], (long)in_sizes[2],
                                (long)in_sizes[3], (long)in_sizes[4], (long)in_sizes[5],
                                (long)in_sizes[6], (float*)d_out);
}

// round 7
// speedup vs baseline: 1.0725x; 1.0363x over previous
#include <cuda_runtime.h>
#include <cuda_bf16.h>

#define NB 1184   // 8 blocks per SM x 148 SMs
#define NT 256

// Scratch: one partial per block + per-row bias sums + arrival counter.
// Partials/rowsums: every slot written every launch -> deterministic.
// g_count: incremented to NB then reset to 0 by the last block -> replay-safe.
__device__ float g_partials[NB];
__device__ float g_rowsums[128];
__device__ int   g_count = 0;

__device__ __forceinline__ float block_reduce(float v, float* sdata) {
    int tid = threadIdx.x;
    #pragma unroll
    for (int off = 16; off > 0; off >>= 1)
        v += __shfl_down_sync(0xFFFFFFFFu, v, off);
    if ((tid & 31) == 0) sdata[tid >> 5] = v;
    __syncthreads();
    float r = 0.0f;
    if (tid < (NT / 32)) r = sdata[tid];
    if (tid < 32) {
        #pragma unroll
        for (int off = (NT / 64); off > 0; off >>= 1)
            r += __shfl_down_sync(0xFFFFFFFFu, r, off);
    }
    return r;  // valid in tid 0
}

// Block partition boundaries: tensor t owns blocks [b_starts[t], b_starts[t+1])
__global__ __launch_bounds__(NT, 8)
void wr_fused_kernel(const float* __restrict__ wq, const float* __restrict__ wk,
                     const float* __restrict__ wv, const float* __restrict__ wo,
                     const float* __restrict__ w1, const float* __restrict__ w2,
                     const float* __restrict__ embed, const float* __restrict__ biases,
                     long n0, long n1, long n2, long n3, long n4, long n5, long n6,
                     int b1, int b2, int b3, int b4, int b5, int b6,  // boundaries (b0=0, b7=NB)
                     float* __restrict__ out)
{
    __shared__ float sdata[NT / 32];
    const float* ptrs[7] = {wq, wk, wv, wo, w1, w2, embed};
    const long ns[7]     = {n0, n1, n2, n3, n4, n5, n6};
    const int  bs[8]     = {0, b1, b2, b3, b4, b5, b6, NB};

    const int bid = blockIdx.x;
    const int tid = threadIdx.x;

    // Which tensor does this block own?
    int t = 0;
    #pragma unroll
    for (int k = 1; k < 7; k++) if (bid >= bs[k]) t = k;

    const float4* __restrict__ p = (const float4*)ptrs[t];
    const long n4e   = ns[t] >> 2;
    const int  nblk  = bs[t + 1] - bs[t];
    const int  lb    = bid - bs[t];
    const long chunk = (n4e + nblk - 1) / nblk;
    const long lo    = (long)lb * chunk;
    const long hi    = (lo + chunk < n4e) ? (lo + chunk) : n4e;

    // 4x unrolled, 4 independent accumulators -> 4 outstanding LDG.128/thread
    float s0 = 0.0f, s1 = 0.0f, s2 = 0.0f, s3 = 0.0f;
    long i = lo + tid;
    for (; i + 3 * NT < hi; i += 4 * NT) {
        float4 a = p[i];
        float4 b = p[i + NT];
        float4 c = p[i + 2 * NT];
        float4 d = p[i + 3 * NT];
        s0 = fmaf(a.x, a.x, s0); s0 = fmaf(a.y, a.y, s0);
        s0 = fmaf(a.z, a.z, s0); s0 = fmaf(a.w, a.w, s0);
        s1 = fmaf(b.x, b.x, s1); s1 = fmaf(b.y, b.y, s1);
        s1 = fmaf(b.z, b.z, s1); s1 = fmaf(b.w, b.w, s1);
        s2 = fmaf(c.x, c.x, s2); s2 = fmaf(c.y, c.y, s2);
        s2 = fmaf(c.z, c.z, s2); s2 = fmaf(c.w, c.w, s2);
        s3 = fmaf(d.x, d.x, s3); s3 = fmaf(d.y, d.y, s3);
        s3 = fmaf(d.z, d.z, s3); s3 = fmaf(d.w, d.w, s3);
    }
    for (; i < hi; i += NT) {
        float4 v = p[i];
        s0 = fmaf(v.x, v.x, s0); s0 = fmaf(v.y, v.y, s0);
        s0 = fmaf(v.z, v.z, s0); s0 = fmaf(v.w, v.w, s0);
    }
    float s = (s0 + s1) + (s2 + s3);

    float r = block_reduce(s, sdata);
    if (tid == 0) g_partials[bid] = r;

    // Bias rows: blocks 0..127 each do one 8KB row (2% extra for those blocks)
    if (bid < 128) {
        __syncthreads();  // sdata reuse
        const float4* __restrict__ pb = (const float4*)(biases) + (long)bid * 512;
        float sb = 0.0f;
        for (int j = tid; j < 512; j += NT) {
            float4 v = pb[j];
            sb = fmaf(v.x, v.x, sb); sb = fmaf(v.y, v.y, sb);
            sb = fmaf(v.z, v.z, sb); sb = fmaf(v.w, v.w, sb);
        }
        float rb = block_reduce(sb, sdata);
        if (tid == 0) g_rowsums[bid] = rb;
    }

    // ---- last-block finalize (partials are L2-hot) ----
    __shared__ bool is_last;
    __threadfence();
    if (tid == 0) {
        int c = atomicAdd(&g_count, 1);
        is_last = (c == (int)gridDim.x - 1);
    }
    __syncthreads();
    if (!is_last) return;
    __threadfence();  // acquire side

    __shared__ float s_total;
    if (tid == 0) s_total = 0.0f;
    __syncthreads();

    #pragma unroll 1
    for (int tt = 0; tt < 7; tt++) {
        float sv = 0.0f;
        for (int j = bs[tt] + tid; j < bs[tt + 1]; j += NT) sv += g_partials[j];
        float rv = block_reduce(sv, sdata);
        if (tid == 0) s_total += sqrtf(rv);
        __syncthreads();
    }

    float s2v = 0.0f;
    for (int j = tid; j < 128; j += NT) s2v += sqrtf(g_rowsums[j]);
    float rb2 = block_reduce(s2v, sdata);
    if (tid == 0) {
        out[0] = 0.0001f * ((s_total + rb2) / 135.0f);  // 7 mats + 128 rows
        g_count = 0;  // reset for next graph replay
    }
}

extern "C" void kernel_launch(void* const* d_in, const int* in_sizes, int n_in,
                              void* d_out, int out_size)
{
    const float* wq     = (const float*)d_in[0];
    const float* wk     = (const float*)d_in[1];
    const float* wv     = (const float*)d_in[2];
    const float* wo     = (const float*)d_in[3];
    const float* w1     = (const float*)d_in[4];
    const float* w2     = (const float*)d_in[5];
    const float* embed  = (const float*)d_in[6];
    const float* biases = (const float*)d_in[7];

    long n[7];
    long total = 0;
    for (int t = 0; t < 7; t++) { n[t] = (long)in_sizes[t]; total += n[t]; }

    // Proportional block partition: boundary[t] = round(cumsum * NB / total)
    int bnd[8];
    bnd[0] = 0;
    long cum = 0;
    for (int t = 0; t < 7; t++) {
        cum += n[t];
        long b = (cum * NB + total / 2) / total;
        if (b <= bnd[t]) b = bnd[t] + 1;   // at least 1 block per tensor
        if (b > NB) b = NB;
        bnd[t + 1] = (int)b;
    }
    bnd[7] = NB;

    wr_fused_kernel<<<NB, NT>>>(wq, wk, wv, wo, w1, w2, embed, biases,
                                n[0], n[1], n[2], n[3], n[4], n[5], n[6],
                                bnd[1], bnd[2], bnd[3], bnd[4], bnd[5], bnd[6],
                                (float*)d_out);
}

// round 9
// speedup vs baseline: 1.1509x; 1.0731x over previous
#include <cuda_runtime.h>
#include <cuda_bf16.h>

#define NB 1184   // 8 resident "slots" x 148 SMs (one wave at occ>=5 too: 1184/148=8/SM? no — occ 5 -> 2 waves of 740; equal chunks keep waves balanced)
#define NT 256

// Scratch: one partial per block + per-row bias sums + arrival counter.
__device__ float g_partials[NB];
__device__ float g_rowsums[128];
__device__ int   g_count = 0;

__device__ __forceinline__ float block_reduce(float v, float* sdata) {
    int tid = threadIdx.x;
    #pragma unroll
    for (int off = 16; off > 0; off >>= 1)
        v += __shfl_down_sync(0xFFFFFFFFu, v, off);
    if ((tid & 31) == 0) sdata[tid >> 5] = v;
    __syncthreads();
    float r = 0.0f;
    if (tid < (NT / 32)) r = sdata[tid];
    if (tid < 32) {
        #pragma unroll
        for (int off = (NT / 64); off > 0; off >>= 1)
            r += __shfl_down_sync(0xFFFFFFFFu, r, off);
    }
    return r;  // valid in tid 0
}

__device__ __forceinline__ float sq4(float4 v, float s) {
    s = fmaf(v.x, v.x, s); s = fmaf(v.y, v.y, s);
    s = fmaf(v.z, v.z, s); s = fmaf(v.w, v.w, s);
    return s;
}

// Block partition boundaries: tensor t owns blocks [bs[t], bs[t+1])
__global__ __launch_bounds__(NT, 5)
void wr_fused_kernel(const float* __restrict__ wq, const float* __restrict__ wk,
                     const float* __restrict__ wv, const float* __restrict__ wo,
                     const float* __restrict__ w1, const float* __restrict__ w2,
                     const float* __restrict__ embed, const float* __restrict__ biases,
                     long n0, long n1, long n2, long n3, long n4, long n5, long n6,
                     int b1, int b2, int b3, int b4, int b5, int b6,
                     float* __restrict__ out)
{
    __shared__ float sdata[NT / 32];
    const float* ptrs[7] = {wq, wk, wv, wo, w1, w2, embed};
    const long ns[7]     = {n0, n1, n2, n3, n4, n5, n6};
    const int  bs[8]     = {0, b1, b2, b3, b4, b5, b6, NB};

    const int bid = blockIdx.x;
    const int tid = threadIdx.x;

    int t = 0;
    #pragma unroll
    for (int k = 1; k < 7; k++) if (bid >= bs[k]) t = k;

    const float4* __restrict__ p = (const float4*)ptrs[t];
    const long n4e   = ns[t] >> 2;
    const int  nblk  = bs[t + 1] - bs[t];
    const int  lb    = bid - bs[t];
    const long chunk = (n4e + nblk - 1) / nblk;
    const long lo    = (long)lb * chunk;
    const long hi    = (lo + chunk < n4e) ? (lo + chunk) : n4e;

    // 8 independent evict-first (streaming) LDG.128 per batch -> high MLP_p1
    float s0 = 0.f, s1 = 0.f, s2 = 0.f, s3 = 0.f;
    float s4 = 0.f, s5 = 0.f, s6 = 0.f, s7 = 0.f;
    long i = lo + tid;
    for (; i + 7 * NT < hi; i += 8 * NT) {
        float4 a = __ldcs(p + i);
        float4 b = __ldcs(p + i + NT);
        float4 c = __ldcs(p + i + 2 * NT);
        float4 d = __ldcs(p + i + 3 * NT);
        float4 e = __ldcs(p + i + 4 * NT);
        float4 f = __ldcs(p + i + 5 * NT);
        float4 g = __ldcs(p + i + 6 * NT);
        float4 h = __ldcs(p + i + 7 * NT);
        s0 = sq4(a, s0); s1 = sq4(b, s1); s2 = sq4(c, s2); s3 = sq4(d, s3);
        s4 = sq4(e, s4); s5 = sq4(f, s5); s6 = sq4(g, s6); s7 = sq4(h, s7);
    }
    for (; i < hi; i += NT) s0 = sq4(__ldcs(p + i), s0);
    float s = ((s0 + s1) + (s2 + s3)) + ((s4 + s5) + (s6 + s7));

    float r = block_reduce(s, sdata);
    if (tid == 0) g_partials[bid] = r;

    // Bias rows: blocks 0..127 each do one 8KB row
    if (bid < 128) {
        __syncthreads();  // sdata reuse
        const float4* __restrict__ pb = (const float4*)(biases) + (long)bid * 512;
        float sb = 0.0f;
        for (int j = tid; j < 512; j += NT) sb = sq4(__ldcs(pb + j), sb);
        float rb = block_reduce(sb, sdata);
        if (tid == 0) g_rowsums[bid] = rb;
    }

    // ---- last-block finalize (partials are L2-hot) ----
    __shared__ bool is_last;
    __threadfence();
    if (tid == 0) {
        int c = atomicAdd(&g_count, 1);
        is_last = (c == (int)gridDim.x - 1);
    }
    __syncthreads();
    if (!is_last) return;
    __threadfence();  // acquire side

    __shared__ float s_total;
    if (tid == 0) s_total = 0.0f;
    __syncthreads();

    #pragma unroll 1
    for (int tt = 0; tt < 7; tt++) {
        float sv = 0.0f;
        for (int j = bs[tt] + tid; j < bs[tt + 1]; j += NT) sv += g_partials[j];
        float rv = block_reduce(sv, sdata);
        if (tid == 0) s_total += sqrtf(rv);
        __syncthreads();
    }

    float s2v = 0.0f;
    for (int j = tid; j < 128; j += NT) s2v += sqrtf(g_rowsums[j]);
    float rb2 = block_reduce(s2v, sdata);
    if (tid == 0) {
        out[0] = 0.0001f * ((s_total + rb2) / 135.0f);  // 7 mats + 128 rows
        g_count = 0;  // reset for next graph replay
    }
}

extern "C" void kernel_launch(void* const* d_in, const int* in_sizes, int n_in,
                              void* d_out, int out_size)
{
    const float* wq     = (const float*)d_in[0];
    const float* wk     = (const float*)d_in[1];
    const float* wv     = (const float*)d_in[2];
    const float* wo     = (const float*)d_in[3];
    const float* w1     = (const float*)d_in[4];
    const float* w2     = (const float*)d_in[5];
    const float* embed  = (const float*)d_in[6];
    const float* biases = (const float*)d_in[7];

    long n[7];
    long total = 0;
    for (int t = 0; t < 7; t++) { n[t] = (long)in_sizes[t]; total += n[t]; }

    int bnd[8];
    bnd[0] = 0;
    long cum = 0;
    for (int t = 0; t < 7; t++) {
        cum += n[t];
        long b = (cum * NB + total / 2) / total;
        if (b <= bnd[t]) b = bnd[t] + 1;
        if (b > NB) b = NB;
        bnd[t + 1] = (int)b;
    }
    bnd[7] = NB;

    wr_fused_kernel<<<NB, NT>>>(wq, wk, wv, wo, w1, w2, embed, biases,
                                n[0], n[1], n[2], n[3], n[4], n[5], n[6],
                                bnd[1], bnd[2], bnd[3], bnd[4], bnd[5], bnd[6],
                                (float*)d_out);
}

// round 10
// speedup vs baseline: 1.2255x; 1.0648x over previous
#include <cuda_runtime.h>
#include <cuda_bf16.h>

#define NB 740    // exactly one wave: 5 CTAs/SM (launch_bounds) x 148 SMs
#define NT 256

// Scratch: one partial per block + per-row bias sums + arrival counter.
__device__ float g_partials[NB];
__device__ float g_rowsums[128];
__device__ int   g_count = 0;

__device__ __forceinline__ float block_reduce(float v, float* sdata) {
    int tid = threadIdx.x;
    #pragma unroll
    for (int off = 16; off > 0; off >>= 1)
        v += __shfl_down_sync(0xFFFFFFFFu, v, off);
    if ((tid & 31) == 0) sdata[tid >> 5] = v;
    __syncthreads();
    float r = 0.0f;
    if (tid < (NT / 32)) r = sdata[tid];
    if (tid < 32) {
        #pragma unroll
        for (int off = (NT / 64); off > 0; off >>= 1)
            r += __shfl_down_sync(0xFFFFFFFFu, r, off);
    }
    return r;  // valid in tid 0
}

__device__ __forceinline__ float sq4(float4 v, float s) {
    s = fmaf(v.x, v.x, s); s = fmaf(v.y, v.y, s);
    s = fmaf(v.z, v.z, s); s = fmaf(v.w, v.w, s);
    return s;
}

// Block partition boundaries: tensor t owns blocks [bs[t], bs[t+1])
__global__ __launch_bounds__(NT, 5)
void wr_fused_kernel(const float* __restrict__ wq, const float* __restrict__ wk,
                     const float* __restrict__ wv, const float* __restrict__ wo,
                     const float* __restrict__ w1, const float* __restrict__ w2,
                     const float* __restrict__ embed, const float* __restrict__ biases,
                     long n0, long n1, long n2, long n3, long n4, long n5, long n6,
                     int b1, int b2, int b3, int b4, int b5, int b6,
                     float* __restrict__ out)
{
    __shared__ float sdata[NT / 32];
    const float* ptrs[7] = {wq, wk, wv, wo, w1, w2, embed};
    const long ns[7]     = {n0, n1, n2, n3, n4, n5, n6};
    const int  bs[8]     = {0, b1, b2, b3, b4, b5, b6, NB};

    const int bid = blockIdx.x;
    const int tid = threadIdx.x;

    int t = 0;
    #pragma unroll
    for (int k = 1; k < 7; k++) if (bid >= bs[k]) t = k;

    const float4* __restrict__ p = (const float4*)ptrs[t];
    const long n4e   = ns[t] >> 2;
    const int  nblk  = bs[t + 1] - bs[t];
    const int  lb    = bid - bs[t];
    const long chunk = (n4e + nblk - 1) / nblk;
    const long lo    = (long)lb * chunk;
    const long hi    = (lo + chunk < n4e) ? (lo + chunk) : n4e;

    // 8 independent evict-first (streaming) LDG.128 per batch -> high MLP_p1
    float s0 = 0.f, s1 = 0.f, s2 = 0.f, s3 = 0.f;
    float s4 = 0.f, s5 = 0.f, s6 = 0.f, s7 = 0.f;
    long i = lo + tid;
    for (; i + 7 * NT < hi; i += 8 * NT) {
        float4 a = __ldcs(p + i);
        float4 b = __ldcs(p + i + NT);
        float4 c = __ldcs(p + i + 2 * NT);
        float4 d = __ldcs(p + i + 3 * NT);
        float4 e = __ldcs(p + i + 4 * NT);
        float4 f = __ldcs(p + i + 5 * NT);
        float4 g = __ldcs(p + i + 6 * NT);
        float4 h = __ldcs(p + i + 7 * NT);
        s0 = sq4(a, s0); s1 = sq4(b, s1); s2 = sq4(c, s2); s3 = sq4(d, s3);
        s4 = sq4(e, s4); s5 = sq4(f, s5); s6 = sq4(g, s6); s7 = sq4(h, s7);
    }
    for (; i < hi; i += NT) s0 = sq4(__ldcs(p + i), s0);
    float s = ((s0 + s1) + (s2 + s3)) + ((s4 + s5) + (s6 + s7));

    float r = block_reduce(s, sdata);
    if (tid == 0) g_partials[bid] = r;

    // Bias rows: blocks 0..127 each do one 8KB row (negligible vs 630KB chunk)
    if (bid < 128) {
        __syncthreads();  // sdata reuse
        const float4* __restrict__ pb = (const float4*)(biases) + (long)bid * 512;
        float sb = 0.0f;
        for (int j = tid; j < 512; j += NT) sb = sq4(__ldcs(pb + j), sb);
        float rb = block_reduce(sb, sdata);
        if (tid == 0) g_rowsums[bid] = rb;
    }

    // ---- last-block finalize (partials are L2-hot) ----
    __shared__ bool is_last;
    __threadfence();
    if (tid == 0) {
        int c = atomicAdd(&g_count, 1);
        is_last = (c == (int)gridDim.x - 1);
    }
    __syncthreads();
    if (!is_last) return;
    __threadfence();  // acquire side

    __shared__ float s_total;
    if (tid == 0) s_total = 0.0f;
    __syncthreads();

    #pragma unroll 1
    for (int tt = 0; tt < 7; tt++) {
        float sv = 0.0f;
        for (int j = bs[tt] + tid; j < bs[tt + 1]; j += NT) sv += g_partials[j];
        float rv = block_reduce(sv, sdata);
        if (tid == 0) s_total += sqrtf(rv);
        __syncthreads();
    }

    float s2v = 0.0f;
    for (int j = tid; j < 128; j += NT) s2v += sqrtf(g_rowsums[j]);
    float rb2 = block_reduce(s2v, sdata);
    if (tid == 0) {
        out[0] = 0.0001f * ((s_total + rb2) / 135.0f);  // 7 mats + 128 rows
        g_count = 0;  // reset for next graph replay
    }
}

extern "C" void kernel_launch(void* const* d_in, const int* in_sizes, int n_in,
                              void* d_out, int out_size)
{
    const float* wq     = (const float*)d_in[0];
    const float* wk     = (const float*)d_in[1];
    const float* wv     = (const float*)d_in[2];
    const float* wo     = (const float*)d_in[3];
    const float* w1     = (const float*)d_in[4];
    const float* w2     = (const float*)d_in[5];
    const float* embed  = (const float*)d_in[6];
    const float* biases = (const float*)d_in[7];

    long n[7];
    long total = 0;
    for (int t = 0; t < 7; t++) { n[t] = (long)in_sizes[t]; total += n[t]; }

    // Proportional block partition over exactly one wave of NB blocks
    int bnd[8];
    bnd[0] = 0;
    long cum = 0;
    for (int t = 0; t < 7; t++) {
        cum += n[t];
        long b = (cum * NB + total / 2) / total;
        if (b <= bnd[t]) b = bnd[t] + 1;
        if (b > NB) b = NB;
        bnd[t + 1] = (int)b;
    }
    bnd[7] = NB;

    wr_fused_kernel<<<NB, NT>>>(wq, wk, wv, wo, w1, w2, embed, biases,
                                n[0], n[1], n[2], n[3], n[4], n[5], n[6],
                                bnd[1], bnd[2], bnd[3], bnd[4], bnd[5], bnd[6],
                                (float*)d_out);
}

// round 12
// speedup vs baseline: 1.2642x; 1.0316x over previous
#include <cuda_runtime.h>
#include <cuda_bf16.h>

#define NT   256
#define NBLK 740      // exactly one wave: 5 CTAs/SM x 148 SMs
#define MAXU 16384    // max work units (unit size auto-scales if exceeded)

// Scratch. Unit partials: every slot in [0, NU) written every launch.
// Counters reset by the last block -> graph-replay deterministic.
__device__ float g_unit_partials[MAXU];
__device__ float g_rowsums[128];
__device__ int   g_ticket = 0;
__device__ int   g_count  = 0;

__device__ __forceinline__ float block_reduce(float v, float* sdata) {
    int tid = threadIdx.x;
    #pragma unroll
    for (int off = 16; off > 0; off >>= 1)
        v += __shfl_down_sync(0xFFFFFFFFu, v, off);
    if ((tid & 31) == 0) sdata[tid >> 5] = v;
    __syncthreads();
    float r = 0.0f;
    if (tid < (NT / 32)) r = sdata[tid];
    if (tid < 32) {
        #pragma unroll
        for (int off = (NT / 64); off > 0; off >>= 1)
            r += __shfl_down_sync(0xFFFFFFFFu, r, off);
    }
    return r;  // valid in tid 0
}

__device__ __forceinline__ float sq4(float4 v, float s) {
    s = fmaf(v.x, v.x, s); s = fmaf(v.y, v.y, s);
    s = fmaf(v.z, v.z, s); s = fmaf(v.w, v.w, s);
    return s;
}

// Unit boundaries: tensor t owns units [ub[t], ub[t+1]); NU = ub[7].
__global__ __launch_bounds__(NT, 5)
void wr_fused_kernel(const float* __restrict__ wq, const float* __restrict__ wk,
                     const float* __restrict__ wv, const float* __restrict__ wo,
                     const float* __restrict__ w1, const float* __restrict__ w2,
                     const float* __restrict__ embed, const float* __restrict__ biases,
                     long n0, long n1, long n2, long n3, long n4, long n5, long n6,
                     int u1, int u2, int u3, int u4, int u5, int u6, int u7,
                     int unit_f4,
                     float* __restrict__ out)
{
    __shared__ float sdata[NT / 32];
    __shared__ int   s_u;
    const float* ptrs[7] = {wq, wk, wv, wo, w1, w2, embed};
    const long ns[7]     = {n0, n1, n2, n3, n4, n5, n6};
    const int  ub[8]     = {0, u1, u2, u3, u4, u5, u6, u7};
    const int  NU        = u7;
    const int  tid       = threadIdx.x;
    const int  bid       = blockIdx.x;

    // ---- dynamic work-stealing over fixed 32KB units ----
    if (tid == 0) s_u = atomicAdd(&g_ticket, 1);
    __syncthreads();
    int u = s_u;
    while (u < NU) {
        int t = 0;
        #pragma unroll
        for (int k = 1; k < 7; k++) if (u >= ub[k]) t = k;
        const float4* __restrict__ p = (const float4*)ptrs[t];
        const long n4e = ns[t] >> 2;
        const long lo  = (long)(u - ub[t]) * unit_f4;
        long hi = lo + unit_f4; if (hi > n4e) hi = n4e;

        float s0 = 0.f, s1 = 0.f, s2 = 0.f, s3 = 0.f;
        float s4 = 0.f, s5 = 0.f, s6 = 0.f, s7 = 0.f;
        long i = lo + tid;
        for (; i + 7 * NT < hi; i += 8 * NT) {
            float4 a = __ldcs(p + i);
            float4 b = __ldcs(p + i + NT);
            float4 c = __ldcs(p + i + 2 * NT);
            float4 d = __ldcs(p + i + 3 * NT);
            float4 e = __ldcs(p + i + 4 * NT);
            float4 f = __ldcs(p + i + 5 * NT);
            float4 g = __ldcs(p + i + 6 * NT);
            float4 h = __ldcs(p + i + 7 * NT);
            // prefetch next ticket early in the first batch (overlaps fma/reduce)
            s0 = sq4(a, s0); s1 = sq4(b, s1); s2 = sq4(c, s2); s3 = sq4(d, s3);
            s4 = sq4(e, s4); s5 = sq4(f, s5); s6 = sq4(g, s6); s7 = sq4(h, s7);
        }
        for (; i < hi; i += NT) s0 = sq4(__ldcs(p + i), s0);

        __syncthreads();  // all threads consumed s_u
        if (tid == 0) s_u = atomicAdd(&g_ticket, 1);  // latency overlaps reduce

        float s = ((s0 + s1) + (s2 + s3)) + ((s4 + s5) + (s6 + s7));
        float r = block_reduce(s, sdata);
        if (tid == 0) g_unit_partials[u] = r;
        __syncthreads();
        u = s_u;
    }

    // Bias rows: blocks 0..127 each do one 8KB row
    if (bid < 128) {
        const float4* __restrict__ pb = (const float4*)(biases) + (long)bid * 512;
        float sb = 0.0f;
        for (int j = tid; j < 512; j += NT) sb = sq4(__ldcs(pb + j), sb);
        float rb = block_reduce(sb, sdata);
        if (tid == 0) g_rowsums[bid] = rb;
        __syncthreads();
    }

    // ---- last-block finalize (unit partials are L2-hot) ----
    __shared__ bool is_last;
    __threadfence();
    if (tid == 0) {
        int c = atomicAdd(&g_count, 1);
        is_last = (c == (int)gridDim.x - 1);
    }
    __syncthreads();
    if (!is_last) return;
    __threadfence();  // acquire side

    __shared__ float s_total;
    if (tid == 0) s_total = 0.0f;
    __syncthreads();

    #pragma unroll 1
    for (int tt = 0; tt < 7; tt++) {
        float sv = 0.0f;
        #pragma unroll 4
        for (int j = ub[tt] + tid; j < ub[tt + 1]; j += NT) sv += g_unit_partials[j];
        // scalar tail (n % 4): empty for these shapes
        if (tid == 0) {
            const float* pf = ptrs[tt];
            const long n = ns[tt];
            for (long j = (n >> 2) << 2; j < n; j++) sv = fmaf(pf[j], pf[j], sv);
        }
        float rv = block_reduce(sv, sdata);
        if (tid == 0) s_total += sqrtf(rv);
        __syncthreads();
    }

    float s2v = 0.0f;
    for (int j = tid; j < 128; j += NT) s2v += sqrtf(g_rowsums[j]);
    float rb2 = block_reduce(s2v, sdata);
    if (tid == 0) {
        out[0] = 0.0001f * ((s_total + rb2) / 135.0f);  // 7 mats + 128 rows
        g_ticket = 0;  // reset for next graph replay
        g_count  = 0;
    }
}

extern "C" void kernel_launch(void* const* d_in, const int* in_sizes, int n_in,
                              void* d_out, int out_size)
{
    const float* wq     = (const float*)d_in[0];
    const float* wk     = (const float*)d_in[1];
    const float* wv     = (const float*)d_in[2];
    const float* wo     = (const float*)d_in[3];
    const float* w1     = (const float*)d_in[4];
    const float* w2     = (const float*)d_in[5];
    const float* embed  = (const float*)d_in[6];
    const float* biases = (const float*)d_in[7];

    long n[7];
    for (int t = 0; t < 7; t++) n[t] = (long)in_sizes[t];

    // Unit size: 2048 float4 (32KB) = one MLP8 batch per thread; grow if NU > MAXU.
    int unit_f4 = 2048;
    int ub[8];
    for (;;) {
        ub[0] = 0;
        for (int t = 0; t < 7; t++) {
            long n4e = n[t] >> 2;
            long nu  = (n4e + unit_f4 - 1) / unit_f4;
            ub[t + 1] = ub[t] + (int)nu;
        }
        if (ub[7] <= MAXU) break;
        unit_f4 <<= 1;
    }

    wr_fused_kernel<<<NBLK, NT>>>(wq, wk, wv, wo, w1, w2, embed, biases,
                                  n[0], n[1], n[2], n[3], n[4], n[5], n[6],
                                  ub[1], ub[2], ub[3], ub[4], ub[5], ub[6], ub[7],
                                  unit_f4, (float*)d_out);
}